// round 1
// baseline (speedup 1.0000x reference)
#include <cuda_runtime.h>
#include <math.h>

#define NMAX 50000
#define EMAX 800000

// ---------------- scratch (device globals; no allocation allowed) ------------
__device__ float        d_h1[NMAX * 256];   // layer1 transformed features
__device__ float        d_al1[NMAX * 4];
__device__ float        d_ar1[NMAX * 4];
__device__ float        d_g1[NMAX];
__device__ unsigned int d_m1[NMAX * 4];     // encoded segment max
__device__ float        d_s1[NMAX * 4];     // segment exp-sum
__device__ float        d_w1[EMAX * 4];     // per-edge exp weights
__device__ float        d_o1[NMAX * 256];   // raw aggregate layer1
__device__ float        d_x2[NMAX * 256];   // elu(normalized out1) = layer2 input
__device__ float        d_h2[NMAX * 64];
__device__ float        d_al2[NMAX];
__device__ float        d_ar2[NMAX];
__device__ float        d_g2[NMAX];
__device__ unsigned int d_m2[NMAX];
__device__ float        d_s2[NMAX];
__device__ float        d_w2[EMAX];
__device__ float        d_o2[NMAX * 64];

// ---------------- helpers ----------------------------------------------------
__device__ __forceinline__ unsigned int enc_f(float f) {
    unsigned int u = __float_as_uint(f);
    return (u & 0x80000000u) ? ~u : (u | 0x80000000u);
}
__device__ __forceinline__ float dec_f(unsigned int u) {
    return (u & 0x80000000u) ? __uint_as_float(u ^ 0x80000000u)
                             : __uint_as_float(~u);
}
// vectorized global float4 reduction (sm_90+)
__device__ __forceinline__ void red_add_v4(float* p, float4 v) {
    asm volatile("red.global.add.v4.f32 [%0], {%1, %2, %3, %4};"
                 :: "l"(p), "f"(v.x), "f"(v.y), "f"(v.z), "f"(v.w)
                 : "memory");
}

// ---------------- simple tiled SGEMM: C[N,M] = A[N,K] @ B[K,M] ----------------
// 64x64 tile, BK=32, 256 threads, 4x4 register micro-tile. K, M multiples of 32/64.
__global__ void sgemm64(const float* __restrict__ A, const float* __restrict__ B,
                        float* __restrict__ C, int N, int K, int M) {
    __shared__ float As[64][33];
    __shared__ float Bs[32][64];
    int tx = threadIdx.x & 15;
    int ty = threadIdx.x >> 4;
    int row0 = blockIdx.y * 64;
    int col0 = blockIdx.x * 64;
    float acc[4][4] = {};
    for (int k0 = 0; k0 < K; k0 += 32) {
        #pragma unroll
        for (int i = 0; i < 2; i++) {
            int idx = threadIdx.x + i * 256;   // float4 index within tile [0,512)
            int r = idx >> 3;
            int c = (idx & 7) * 4;
            float4 v = make_float4(0.f, 0.f, 0.f, 0.f);
            if (row0 + r < N)
                v = *(const float4*)&A[(size_t)(row0 + r) * K + k0 + c];
            As[r][c] = v.x; As[r][c + 1] = v.y; As[r][c + 2] = v.z; As[r][c + 3] = v.w;
        }
        #pragma unroll
        for (int i = 0; i < 2; i++) {
            int idx = threadIdx.x + i * 256;
            int r = idx >> 4;
            int c = (idx & 15) * 4;
            *(float4*)&Bs[r][c] = *(const float4*)&B[(size_t)(k0 + r) * M + col0 + c];
        }
        __syncthreads();
        #pragma unroll
        for (int k = 0; k < 32; k++) {
            float a[4], b[4];
            #pragma unroll
            for (int i = 0; i < 4; i++) a[i] = As[ty * 4 + i][k];
            #pragma unroll
            for (int j = 0; j < 4; j++) b[j] = Bs[k][tx * 4 + j];
            #pragma unroll
            for (int i = 0; i < 4; i++)
                #pragma unroll
                for (int j = 0; j < 4; j++)
                    acc[i][j] += a[i] * b[j];
        }
        __syncthreads();
    }
    #pragma unroll
    for (int i = 0; i < 4; i++) {
        int r = row0 + ty * 4 + i;
        if (r < N) {
            #pragma unroll
            for (int j = 0; j < 4; j++)
                C[(size_t)r * M + col0 + tx * 4 + j] = acc[i][j];
        }
    }
}

// ---------------- layer1 node prep: al/ar dot-products + guidance -------------
__global__ void node_prep1(const float* __restrict__ x,
                           const float* __restrict__ attl,
                           const float* __restrict__ attr, int N) {
    int w = (blockIdx.x * blockDim.x + threadIdx.x) >> 5;
    int lane = threadIdx.x & 31;
    if (w >= N) return;
    const float* hrow = &d_h1[(size_t)w * 256];
    float aL[4] = {0.f, 0.f, 0.f, 0.f}, aR[4] = {0.f, 0.f, 0.f, 0.f};
    #pragma unroll
    for (int i = 0; i < 8; i++) {
        int idx = lane + i * 32;
        float hv = hrow[idx];
        int h = idx >> 6;
        aL[h] += hv * attl[idx];
        aR[h] += hv * attr[idx];
    }
    #pragma unroll
    for (int h = 0; h < 4; h++) {
        #pragma unroll
        for (int off = 16; off; off >>= 1) {
            aL[h] += __shfl_xor_sync(0xffffffffu, aL[h], off);
            aR[h] += __shfl_xor_sync(0xffffffffu, aR[h], off);
        }
    }
    if (lane == 0) {
        #pragma unroll
        for (int h = 0; h < 4; h++) {
            d_al1[w * 4 + h] = aL[h];
            d_ar1[w * 4 + h] = aR[h];
        }
        // normalization constant of rw cancels in segment softmax -> drop it
        d_g1[w] = -0.1f * logf(fabsf(x[(size_t)w * 128 + 127]) + 1e-6f);
    }
}

// ---------------- edge passes (templated over #heads) -------------------------
template <int H>
__global__ void edge_max_k(const int* __restrict__ src, const int* __restrict__ dst,
                           const float* __restrict__ al, const float* __restrict__ ar,
                           const float* __restrict__ g, unsigned int* __restrict__ m,
                           int E) {
    int t = blockIdx.x * blockDim.x + threadIdx.x;
    if (t >= E * H) return;
    int e = t / H, h = t - e * H;
    int s = src[e], d = dst[e];
    float v = al[d * H + h] + ar[s * H + h];
    v = v > 0.f ? v : 0.01f * v;
    v += g[s];
    atomicMax(&m[d * H + h], enc_f(v));
}

template <int H>
__global__ void edge_exp_k(const int* __restrict__ src, const int* __restrict__ dst,
                           const float* __restrict__ al, const float* __restrict__ ar,
                           const float* __restrict__ g,
                           const unsigned int* __restrict__ m,
                           float* __restrict__ ssum, float* __restrict__ wout, int E) {
    int t = blockIdx.x * blockDim.x + threadIdx.x;
    if (t >= E * H) return;
    int e = t / H, h = t - e * H;
    int s = src[e], d = dst[e];
    float v = al[d * H + h] + ar[s * H + h];
    v = v > 0.f ? v : 0.01f * v;
    v += g[s];
    float ex = __expf(v - dec_f(m[d * H + h]));
    wout[e * H + h] = ex;
    atomicAdd(&ssum[d * H + h], ex);
}

// ---------------- layer1 aggregation: warp per edge, 256 floats ---------------
__global__ void edge_agg1(const int* __restrict__ src, const int* __restrict__ dst, int E) {
    int w = (blockIdx.x * blockDim.x + threadIdx.x) >> 5;
    int lane = threadIdx.x & 31;
    if (w >= E) return;
    int s = src[w], d = dst[w];
    const float4* hs = (const float4*)&d_h1[(size_t)s * 256];
    float* od = &d_o1[(size_t)d * 256];
    #pragma unroll
    for (int i = 0; i < 2; i++) {
        int q = lane + i * 32;                 // float4 index in [0,64)
        float wt = d_w1[(size_t)w * 4 + (q >> 4)];
        float4 v = hs[q];
        v.x *= wt; v.y *= wt; v.z *= wt; v.w *= wt;
        red_add_v4(od + q * 4, v);
    }
}

// ---------------- layer1 finish: normalize, elu, guidance for layer2 ----------
__global__ void node_fin1(int N) {
    int i = blockIdx.x * blockDim.x + threadIdx.x;
    if (i >= N * 256) return;
    int n = i >> 8, hc = i & 255;
    int h = hc >> 6;
    float v = d_o1[i] / (d_s1[n * 4 + h] + 1e-16f);
    v = v > 0.f ? v : (__expf(v) - 1.0f);      // elu
    d_x2[i] = v;
    if (hc == 255) d_g2[n] = -0.1f * logf(fabsf(v) + 1e-6f);
}

// ---------------- layer2 node prep -------------------------------------------
__global__ void node_prep2(const float* __restrict__ attl,
                           const float* __restrict__ attr, int N) {
    int w = (blockIdx.x * blockDim.x + threadIdx.x) >> 5;
    int lane = threadIdx.x & 31;
    if (w >= N) return;
    float aL = 0.f, aR = 0.f;
    #pragma unroll
    for (int i = 0; i < 2; i++) {
        int idx = lane + i * 32;
        float hv = d_h2[(size_t)w * 64 + idx];
        aL += hv * attl[idx];
        aR += hv * attr[idx];
    }
    #pragma unroll
    for (int off = 16; off; off >>= 1) {
        aL += __shfl_xor_sync(0xffffffffu, aL, off);
        aR += __shfl_xor_sync(0xffffffffu, aR, off);
    }
    if (lane == 0) { d_al2[w] = aL; d_ar2[w] = aR; }
}

// ---------------- layer2 aggregation: 16 threads per edge, 64 floats ----------
__global__ void edge_agg2(const int* __restrict__ src, const int* __restrict__ dst, int E) {
    int t = blockIdx.x * blockDim.x + threadIdx.x;
    if (t >= E * 16) return;
    int e = t >> 4, q = t & 15;
    int s = src[e], d = dst[e];
    float wt = d_w2[e];
    float4 v = ((const float4*)&d_h2[(size_t)s * 64])[q];
    v.x *= wt; v.y *= wt; v.z *= wt; v.w *= wt;
    red_add_v4(&d_o2[(size_t)d * 64 + q * 4], v);
}

// ---------------- final: normalize, elu, fc -----------------------------------
__global__ void node_final(const float* __restrict__ fcw, const float* __restrict__ fcb,
                           float* __restrict__ out, int N) {
    int w = (blockIdx.x * blockDim.x + threadIdx.x) >> 5;
    int lane = threadIdx.x & 31;
    if (w >= N) return;
    float s = d_s2[w] + 1e-16f;
    float acc = 0.f;
    #pragma unroll
    for (int i = 0; i < 2; i++) {
        int idx = lane + i * 32;
        float v = d_o2[(size_t)w * 64 + idx] / s;
        v = v > 0.f ? v : (__expf(v) - 1.0f);  // elu
        acc += v * fcw[idx];
    }
    #pragma unroll
    for (int off = 16; off; off >>= 1)
        acc += __shfl_xor_sync(0xffffffffu, acc, off);
    if (lane == 0) out[w] = acc + fcb[0];
}

// ---------------- host launcher ----------------------------------------------
extern "C" void kernel_launch(void* const* d_in, const int* in_sizes, int n_in,
                              void* d_out, int out_size) {
    const float* x     = (const float*)d_in[0];
    const int*   ei    = (const int*)d_in[1];
    const float* W1    = (const float*)d_in[2];
    const float* attl1 = (const float*)d_in[3];
    const float* attr1 = (const float*)d_in[4];
    const float* W2    = (const float*)d_in[5];
    const float* attl2 = (const float*)d_in[6];
    const float* attr2 = (const float*)d_in[7];
    const float* fcw   = (const float*)d_in[8];
    const float* fcb   = (const float*)d_in[9];
    float* out = (float*)d_out;

    int N = in_sizes[0] / 128;
    int E = in_sizes[1] / 2;
    const int* src = ei;
    const int* dst = ei + E;

    // symbol addresses (host side)
    void *pm1, *ps1, *po1, *pm2, *ps2, *po2;
    void *ph1, *pal1, *par1, *pg1, *pw1;
    void *px2, *ph2, *pal2, *par2, *pg2, *pw2;
    cudaGetSymbolAddress(&pm1, d_m1);
    cudaGetSymbolAddress(&ps1, d_s1);
    cudaGetSymbolAddress(&po1, d_o1);
    cudaGetSymbolAddress(&pm2, d_m2);
    cudaGetSymbolAddress(&ps2, d_s2);
    cudaGetSymbolAddress(&po2, d_o2);
    cudaGetSymbolAddress(&ph1, d_h1);
    cudaGetSymbolAddress(&pal1, d_al1);
    cudaGetSymbolAddress(&par1, d_ar1);
    cudaGetSymbolAddress(&pg1, d_g1);
    cudaGetSymbolAddress(&pw1, d_w1);
    cudaGetSymbolAddress(&px2, d_x2);
    cudaGetSymbolAddress(&ph2, d_h2);
    cudaGetSymbolAddress(&pal2, d_al2);
    cudaGetSymbolAddress(&par2, d_ar2);
    cudaGetSymbolAddress(&pg2, d_g2);
    cudaGetSymbolAddress(&pw2, d_w2);

    const int TB = 256;

    // zero accumulators (encoded -inf == 0 for the max buffers)
    cudaMemsetAsync(pm1, 0, sizeof(unsigned int) * (size_t)N * 4, 0);
    cudaMemsetAsync(ps1, 0, sizeof(float) * (size_t)N * 4, 0);
    cudaMemsetAsync(po1, 0, sizeof(float) * (size_t)N * 256, 0);
    cudaMemsetAsync(pm2, 0, sizeof(unsigned int) * (size_t)N, 0);
    cudaMemsetAsync(ps2, 0, sizeof(float) * (size_t)N, 0);
    cudaMemsetAsync(po2, 0, sizeof(float) * (size_t)N * 64, 0);

    // ---- layer 1 ----
    sgemm64<<<dim3(4, (N + 63) / 64), TB>>>(x, W1, (float*)ph1, N, 128, 256);
    node_prep1<<<(N * 32 + TB - 1) / TB, TB>>>(x, attl1, attr1, N);
    edge_max_k<4><<<(E * 4 + TB - 1) / TB, TB>>>(src, dst, (const float*)pal1,
                                                 (const float*)par1, (const float*)pg1,
                                                 (unsigned int*)pm1, E);
    edge_exp_k<4><<<(E * 4 + TB - 1) / TB, TB>>>(src, dst, (const float*)pal1,
                                                 (const float*)par1, (const float*)pg1,
                                                 (const unsigned int*)pm1,
                                                 (float*)ps1, (float*)pw1, E);
    edge_agg1<<<(E * 32 + TB - 1) / TB, TB>>>(src, dst, E);
    node_fin1<<<(N * 256 + TB - 1) / TB, TB>>>(N);

    // ---- layer 2 ----
    sgemm64<<<dim3(1, (N + 63) / 64), TB>>>((const float*)px2, W2, (float*)ph2, N, 256, 64);
    node_prep2<<<(N * 32 + TB - 1) / TB, TB>>>(attl2, attr2, N);
    edge_max_k<1><<<(E + TB - 1) / TB, TB>>>(src, dst, (const float*)pal2,
                                             (const float*)par2, (const float*)pg2,
                                             (unsigned int*)pm2, E);
    edge_exp_k<1><<<(E + TB - 1) / TB, TB>>>(src, dst, (const float*)pal2,
                                             (const float*)par2, (const float*)pg2,
                                             (const unsigned int*)pm2,
                                             (float*)ps2, (float*)pw2, E);
    edge_agg2<<<(E * 16 + TB - 1) / TB, TB>>>(src, dst, E);
    node_final<<<(N * 32 + TB - 1) / TB, TB>>>(fcw, fcb, out, N);
}

// round 3
// speedup vs baseline: 1.1174x; 1.1174x over previous
#include <cuda_runtime.h>
#include <math.h>

#define NMAX 50000
#define EMAX 800000

// ---------------- scratch (device globals; no allocation allowed) ------------
__device__ float d_h1[NMAX * 256];   // layer1 transformed features
__device__ float d_al1[NMAX * 4];
__device__ float d_ar1[NMAX * 4];
__device__ float d_g1[NMAX];
__device__ float d_s1[NMAX * 4];     // segment exp-sum
__device__ float d_o1[NMAX * 256];   // raw aggregate layer1
__device__ float d_h2[NMAX * 64];
__device__ float d_al2[NMAX];
__device__ float d_ar2[NMAX];
__device__ float d_g2[NMAX];
__device__ float d_s2[NMAX];
__device__ float d_o2[NMAX * 64];

// vectorized global float4 reduction (sm_90+)
__device__ __forceinline__ void red_add_v4(float* p, float4 v) {
    asm volatile("red.global.add.v4.f32 [%0], {%1, %2, %3, %4};"
                 :: "l"(p), "f"(v.x), "f"(v.y), "f"(v.z), "f"(v.w)
                 : "memory");
}
__device__ __forceinline__ float elu_f(float v) {
    return v > 0.f ? v : (__expf(v) - 1.0f);
}

// ---------------- fp32 tiled SGEMM: C[N,M] = A[N,K] @ B[K,M] ------------------
// 64x64 tile, BK=32, 256 threads, 4x4 register micro-tile. K mult of 32, M of 64.
// NORM: fuse per-row/per-head softmax normalization + ELU into the A load
// (layer2 input = elu(o1 / s1)).
template <bool NORM>
__global__ void sgemm64(const float* __restrict__ A, const float* __restrict__ B,
                        float* __restrict__ C, const float* __restrict__ snorm,
                        int N, int K, int M) {
    __shared__ float As[64][33];
    __shared__ float Bs[32][64];
    int tx = threadIdx.x & 15;
    int ty = threadIdx.x >> 4;
    int row0 = blockIdx.y * 64;
    int col0 = blockIdx.x * 64;
    float acc[4][4] = {};
    for (int k0 = 0; k0 < K; k0 += 32) {
        #pragma unroll
        for (int i = 0; i < 2; i++) {
            int idx = threadIdx.x + i * 256;   // float4 index within tile [0,512)
            int r = idx >> 3;
            int c = (idx & 7) * 4;
            int row = row0 + r;
            float4 v = make_float4(0.f, 0.f, 0.f, 0.f);
            if (row < N) {
                v = *(const float4*)&A[(size_t)row * K + k0 + c];
                if (NORM) {
                    float s = snorm[row * 4 + ((k0 + c) >> 6)] + 1e-16f;
                    v.x = elu_f(v.x / s); v.y = elu_f(v.y / s);
                    v.z = elu_f(v.z / s); v.w = elu_f(v.w / s);
                }
            }
            As[r][c] = v.x; As[r][c + 1] = v.y; As[r][c + 2] = v.z; As[r][c + 3] = v.w;
        }
        #pragma unroll
        for (int i = 0; i < 2; i++) {
            int idx = threadIdx.x + i * 256;
            int r = idx >> 4;
            int c = (idx & 15) * 4;
            *(float4*)&Bs[r][c] = *(const float4*)&B[(size_t)(k0 + r) * M + col0 + c];
        }
        __syncthreads();
        #pragma unroll
        for (int k = 0; k < 32; k++) {
            float a[4], b[4];
            #pragma unroll
            for (int i = 0; i < 4; i++) a[i] = As[ty * 4 + i][k];
            #pragma unroll
            for (int j = 0; j < 4; j++) b[j] = Bs[k][tx * 4 + j];
            #pragma unroll
            for (int i = 0; i < 4; i++)
                #pragma unroll
                for (int j = 0; j < 4; j++)
                    acc[i][j] += a[i] * b[j];
        }
        __syncthreads();
    }
    #pragma unroll
    for (int i = 0; i < 4; i++) {
        int r = row0 + ty * 4 + i;
        if (r < N) {
            #pragma unroll
            for (int j = 0; j < 4; j++)
                C[(size_t)r * M + col0 + tx * 4 + j] = acc[i][j];
        }
    }
}

// ---------------- layer1 node prep: al/ar dot-products + guidance -------------
__global__ void node_prep1(const float* __restrict__ x,
                           const float* __restrict__ attl,
                           const float* __restrict__ attr, int N) {
    int w = (blockIdx.x * blockDim.x + threadIdx.x) >> 5;
    int lane = threadIdx.x & 31;
    if (w >= N) return;
    const float* hrow = &d_h1[(size_t)w * 256];
    float aL[4] = {0.f, 0.f, 0.f, 0.f}, aR[4] = {0.f, 0.f, 0.f, 0.f};
    #pragma unroll
    for (int i = 0; i < 8; i++) {
        int idx = lane + i * 32;
        float hv = hrow[idx];
        int h = idx >> 6;
        aL[h] += hv * attl[idx];
        aR[h] += hv * attr[idx];
    }
    #pragma unroll
    for (int h = 0; h < 4; h++) {
        #pragma unroll
        for (int off = 16; off; off >>= 1) {
            aL[h] += __shfl_xor_sync(0xffffffffu, aL[h], off);
            aR[h] += __shfl_xor_sync(0xffffffffu, aR[h], off);
        }
    }
    if (lane == 0) {
        #pragma unroll
        for (int h = 0; h < 4; h++) {
            d_al1[w * 4 + h] = aL[h];
            d_ar1[w * 4 + h] = aR[h];
        }
        // L1-normalization constant of rw cancels in segment softmax -> drop it
        d_g1[w] = -0.1f * logf(fabsf(x[(size_t)w * 128 + 127]) + 1e-6f);
    }
}

// ---------------- layer1 fused exp + sum + aggregation (warp per edge) --------
__global__ void edge_agg1(const int* __restrict__ src, const int* __restrict__ dst, int E) {
    int w = (blockIdx.x * blockDim.x + threadIdx.x) >> 5;
    int lane = threadIdx.x & 31;
    if (w >= E) return;
    int s = src[w], d = dst[w];
    float ex = 0.f;
    if (lane < 4) {
        float v = d_al1[d * 4 + lane] + d_ar1[s * 4 + lane];
        v = v > 0.f ? v : 0.01f * v;            // leaky relu
        v += d_g1[s];                           // guidance (softmax shift-safe)
        ex = __expf(v);                         // no max-subtraction needed
        atomicAdd(&d_s1[d * 4 + lane], ex);
    }
    float wts[4];
    wts[0] = __shfl_sync(0xffffffffu, ex, 0);
    wts[1] = __shfl_sync(0xffffffffu, ex, 1);
    wts[2] = __shfl_sync(0xffffffffu, ex, 2);
    wts[3] = __shfl_sync(0xffffffffu, ex, 3);
    const float4* hs = (const float4*)&d_h1[(size_t)s * 256];
    float* od = &d_o1[(size_t)d * 256];
    #pragma unroll
    for (int i = 0; i < 2; i++) {
        int q = lane + i * 32;                   // float4 index in [0,64)
        float wt = wts[q >> 4];
        float4 v = hs[q];
        v.x *= wt; v.y *= wt; v.z *= wt; v.w *= wt;
        red_add_v4(od + q * 4, v);
    }
}

// ---------------- layer2 node prep: al2/ar2 dots + layer2 guidance ------------
__global__ void node_prep2(const float* __restrict__ attl,
                           const float* __restrict__ attr, int N) {
    int w = (blockIdx.x * blockDim.x + threadIdx.x) >> 5;
    int lane = threadIdx.x & 31;
    if (w >= N) return;
    float aL = 0.f, aR = 0.f;
    #pragma unroll
    for (int i = 0; i < 2; i++) {
        int idx = lane + i * 32;
        float hv = d_h2[(size_t)w * 64 + idx];
        aL += hv * attl[idx];
        aR += hv * attr[idx];
    }
    #pragma unroll
    for (int off = 16; off; off >>= 1) {
        aL += __shfl_xor_sync(0xffffffffu, aL, off);
        aR += __shfl_xor_sync(0xffffffffu, aR, off);
    }
    if (lane == 0) {
        d_al2[w] = aL;
        d_ar2[w] = aR;
        // guidance from layer2 input's last feature = elu(o1[.,255]/s1[.,3])
        float s3 = d_s1[w * 4 + 3] + 1e-16f;
        float v = elu_f(d_o1[(size_t)w * 256 + 255] / s3);
        d_g2[w] = -0.1f * logf(fabsf(v) + 1e-6f);
    }
}

// ---------------- layer2 fused exp + sum + aggregation (16 thr per edge) ------
__global__ void edge_agg2(const int* __restrict__ src, const int* __restrict__ dst, int E) {
    int t = blockIdx.x * blockDim.x + threadIdx.x;
    if (t >= E * 16) return;
    int e = t >> 4, q = t & 15;
    int lane = threadIdx.x & 31;
    int s = src[e], d = dst[e];
    float ex = 0.f;
    if (q == 0) {
        float v = d_al2[d] + d_ar2[s];
        v = v > 0.f ? v : 0.01f * v;
        v += d_g2[s];
        ex = __expf(v);
        atomicAdd(&d_s2[d], ex);
    }
    ex = __shfl_sync(0xffffffffu, ex, lane & 16);  // broadcast from group base
    float4 v = ((const float4*)&d_h2[(size_t)s * 64])[q];
    v.x *= ex; v.y *= ex; v.z *= ex; v.w *= ex;
    red_add_v4(&d_o2[(size_t)d * 64 + q * 4], v);
}

// ---------------- final: normalize, elu, fc -----------------------------------
__global__ void node_final(const float* __restrict__ fcw, const float* __restrict__ fcb,
                           float* __restrict__ out, int N) {
    int w = (blockIdx.x * blockDim.x + threadIdx.x) >> 5;
    int lane = threadIdx.x & 31;
    if (w >= N) return;
    float s = d_s2[w] + 1e-16f;
    float acc = 0.f;
    #pragma unroll
    for (int i = 0; i < 2; i++) {
        int idx = lane + i * 32;
        float v = elu_f(d_o2[(size_t)w * 64 + idx] / s);
        acc += v * fcw[idx];
    }
    #pragma unroll
    for (int off = 16; off; off >>= 1)
        acc += __shfl_xor_sync(0xffffffffu, acc, off);
    if (lane == 0) out[w] = acc + fcb[0];
}

// ---------------- host launcher ----------------------------------------------
extern "C" void kernel_launch(void* const* d_in, const int* in_sizes, int n_in,
                              void* d_out, int out_size) {
    const float* x     = (const float*)d_in[0];
    const int*   ei    = (const int*)d_in[1];
    const float* W1    = (const float*)d_in[2];
    const float* attl1 = (const float*)d_in[3];
    const float* attr1 = (const float*)d_in[4];
    const float* W2    = (const float*)d_in[5];
    const float* attl2 = (const float*)d_in[6];
    const float* attr2 = (const float*)d_in[7];
    const float* fcw   = (const float*)d_in[8];
    const float* fcb   = (const float*)d_in[9];
    float* out = (float*)d_out;

    int N = in_sizes[0] / 128;
    int E = in_sizes[1] / 2;
    const int* src = ei;
    const int* dst = ei + E;

    void *ps1, *po1, *ps2, *po2, *ph1, *ph2;
    cudaGetSymbolAddress(&ps1, d_s1);
    cudaGetSymbolAddress(&po1, d_o1);
    cudaGetSymbolAddress(&ps2, d_s2);
    cudaGetSymbolAddress(&po2, d_o2);
    cudaGetSymbolAddress(&ph1, d_h1);
    cudaGetSymbolAddress(&ph2, d_h2);

    const int TB = 256;
    int gy = (N + 63) / 64;

    cudaMemsetAsync(ps1, 0, sizeof(float) * (size_t)N * 4, 0);
    cudaMemsetAsync(po1, 0, sizeof(float) * (size_t)N * 256, 0);
    cudaMemsetAsync(ps2, 0, sizeof(float) * (size_t)N, 0);
    cudaMemsetAsync(po2, 0, sizeof(float) * (size_t)N * 64, 0);

    // ---- layer 1 ----
    sgemm64<false><<<dim3(4, gy), TB>>>(x, W1, (float*)ph1, nullptr, N, 128, 256);
    node_prep1<<<(N * 32 + TB - 1) / TB, TB>>>(x, attl1, attr1, N);
    edge_agg1<<<(E * 32 + TB - 1) / TB, TB>>>(src, dst, E);

    // ---- layer 2 (normalization + ELU of layer1 output fused into A load) ----
    sgemm64<true><<<dim3(1, gy), TB>>>((const float*)po1, W2, (float*)ph2,
                                       (const float*)ps1, N, 256, 64);
    node_prep2<<<(N * 32 + TB - 1) / TB, TB>>>(attl2, attr2, N);
    edge_agg2<<<(E * 16 + TB - 1) / TB, TB>>>(src, dst, E);
    node_final<<<(N * 32 + TB - 1) / TB, TB>>>(fcw, fcb, out, N);
}

// round 4
// speedup vs baseline: 1.5708x; 1.4057x over previous
#include <cuda_runtime.h>
#include <math.h>

#define NMAX 50000
#define EMAX 800000
#define SB   512   // scan block size

// ---------------- scratch (device globals; no allocation allowed) ------------
__device__ float d_h1[NMAX * 256];   // layer1 transformed features
__device__ float d_al1[NMAX * 4];
__device__ float d_ar1[NMAX * 4];
__device__ float d_g1[NMAX];
__device__ float d_x2[NMAX * 256];   // elu(softmax-normalized aggregate) = GEMM2 input
__device__ float d_h2[NMAX * 64];
__device__ float d_al2[NMAX];
__device__ float d_ar2[NMAX];
__device__ float d_g2[NMAX];
// CSR (edges sorted by destination)
__device__ int   d_deg[NMAX];
__device__ int   d_cur[NMAX];
__device__ int   d_rs[NMAX + 1];
__device__ int   d_bt[(NMAX + SB - 1) / SB];
__device__ int   d_srcs[EMAX];       // source node of each dst-sorted edge

__device__ __forceinline__ float elu_f(float v) {
    return v > 0.f ? v : (__expf(v) - 1.0f);
}

// ---------------- fp32 tiled SGEMM: C[N,M] = A[N,K] @ B[K,M] ------------------
__global__ void sgemm64(const float* __restrict__ A, const float* __restrict__ B,
                        float* __restrict__ C, int N, int K, int M) {
    __shared__ float As[64][33];
    __shared__ float Bs[32][64];
    int tx = threadIdx.x & 15;
    int ty = threadIdx.x >> 4;
    int row0 = blockIdx.y * 64;
    int col0 = blockIdx.x * 64;
    float acc[4][4] = {};
    for (int k0 = 0; k0 < K; k0 += 32) {
        #pragma unroll
        for (int i = 0; i < 2; i++) {
            int idx = threadIdx.x + i * 256;
            int r = idx >> 3;
            int c = (idx & 7) * 4;
            int row = row0 + r;
            float4 v = make_float4(0.f, 0.f, 0.f, 0.f);
            if (row < N) v = *(const float4*)&A[(size_t)row * K + k0 + c];
            As[r][c] = v.x; As[r][c + 1] = v.y; As[r][c + 2] = v.z; As[r][c + 3] = v.w;
        }
        #pragma unroll
        for (int i = 0; i < 2; i++) {
            int idx = threadIdx.x + i * 256;
            int r = idx >> 4;
            int c = (idx & 15) * 4;
            *(float4*)&Bs[r][c] = *(const float4*)&B[(size_t)(k0 + r) * M + col0 + c];
        }
        __syncthreads();
        #pragma unroll
        for (int k = 0; k < 32; k++) {
            float a[4], b[4];
            #pragma unroll
            for (int i = 0; i < 4; i++) a[i] = As[ty * 4 + i][k];
            #pragma unroll
            for (int j = 0; j < 4; j++) b[j] = Bs[k][tx * 4 + j];
            #pragma unroll
            for (int i = 0; i < 4; i++)
                #pragma unroll
                for (int j = 0; j < 4; j++)
                    acc[i][j] += a[i] * b[j];
        }
        __syncthreads();
    }
    #pragma unroll
    for (int i = 0; i < 4; i++) {
        int r = row0 + ty * 4 + i;
        if (r < N) {
            #pragma unroll
            for (int j = 0; j < 4; j++)
                C[(size_t)r * M + col0 + tx * 4 + j] = acc[i][j];
        }
    }
}

// ---------------- CSR build ---------------------------------------------------
__global__ void k_count(const int* __restrict__ dst, int E) {
    int e = blockIdx.x * blockDim.x + threadIdx.x;
    if (e < E) atomicAdd(&d_deg[dst[e]], 1);
}
__global__ void k_scan1(int N) {
    __shared__ int sm[SB];
    int i = blockIdx.x * SB + threadIdx.x;
    int v = (i < N) ? d_deg[i] : 0;
    sm[threadIdx.x] = v;
    __syncthreads();
    #pragma unroll
    for (int off = 1; off < SB; off <<= 1) {
        int t = (threadIdx.x >= off) ? sm[threadIdx.x - off] : 0;
        __syncthreads();
        sm[threadIdx.x] += t;
        __syncthreads();
    }
    if (i < N) d_rs[i] = sm[threadIdx.x] - v;      // exclusive within block
    if (threadIdx.x == SB - 1) d_bt[blockIdx.x] = sm[SB - 1];
}
__global__ void k_scan2(int nb, int E) {
    if (threadIdx.x == 0) {
        int run = 0;
        for (int b = 0; b < nb; b++) { int t = d_bt[b]; d_bt[b] = run; run += t; }
        d_rs[NMAX] = 0;   // unused slot guard
    }
}
__global__ void k_scan3(int N, int E) {
    int i = blockIdx.x * SB + threadIdx.x;
    if (i < N) d_rs[i] += d_bt[blockIdx.x];
    if (i == 0) d_rs[N] = E;
}
__global__ void k_scatter(const int* __restrict__ src, const int* __restrict__ dst, int E) {
    int e = blockIdx.x * blockDim.x + threadIdx.x;
    if (e >= E) return;
    int d = dst[e];
    int pos = d_rs[d] + atomicAdd(&d_cur[d], 1);
    d_srcs[pos] = src[e];
}

// ---------------- layer1 node prep: al/ar dot-products + guidance -------------
__global__ void node_prep1(const float* __restrict__ x,
                           const float* __restrict__ attl,
                           const float* __restrict__ attr, int N) {
    int w = (blockIdx.x * blockDim.x + threadIdx.x) >> 5;
    int lane = threadIdx.x & 31;
    if (w >= N) return;
    const float* hrow = &d_h1[(size_t)w * 256];
    float aL[4] = {0.f, 0.f, 0.f, 0.f}, aR[4] = {0.f, 0.f, 0.f, 0.f};
    #pragma unroll
    for (int i = 0; i < 8; i++) {
        int idx = lane + i * 32;
        float hv = hrow[idx];
        int h = idx >> 6;
        aL[h] += hv * attl[idx];
        aR[h] += hv * attr[idx];
    }
    #pragma unroll
    for (int h = 0; h < 4; h++) {
        #pragma unroll
        for (int off = 16; off; off >>= 1) {
            aL[h] += __shfl_xor_sync(0xffffffffu, aL[h], off);
            aR[h] += __shfl_xor_sync(0xffffffffu, aR[h], off);
        }
    }
    if (lane == 0) {
        #pragma unroll
        for (int h = 0; h < 4; h++) {
            d_al1[w * 4 + h] = aL[h];
            d_ar1[w * 4 + h] = aR[h];
        }
        // L1-normalization constant of rw cancels in segment softmax -> drop it
        d_g1[w] = -0.1f * logf(fabsf(x[(size_t)w * 128 + 127]) + 1e-6f);
    }
}

// ---------------- layer1 CSR aggregation: warp per dst node -------------------
// Register-resident accumulation of 256 features + per-head softmax sums.
// Epilogue: normalize, ELU, single store to x2; compute layer2 guidance g2.
__global__ void agg1_csr(int N) {
    int n = (blockIdx.x * blockDim.x + threadIdx.x) >> 5;
    int lane = threadIdx.x & 31;
    if (n >= N) return;
    int beg = d_rs[n], end = d_rs[n + 1];
    float alh = (lane < 4) ? d_al1[n * 4 + lane] : 0.f;
    float4 accA = make_float4(0.f, 0.f, 0.f, 0.f);
    float4 accB = make_float4(0.f, 0.f, 0.f, 0.f);
    float wsum = 0.f;   // lanes 0-3: per-head exp sums
    for (int p = beg; p < end; p++) {
        int s = d_srcs[p];
        float ex = 0.f;
        if (lane < 4) {
            float v = alh + d_ar1[s * 4 + lane];
            v = v > 0.f ? v : 0.01f * v;        // leaky relu
            v += d_g1[s];                       // guidance (shift-safe softmax)
            ex = __expf(v);
            wsum += ex;
        }
        float w0 = __shfl_sync(0xffffffffu, ex, 0);
        float w1 = __shfl_sync(0xffffffffu, ex, 1);
        float w2 = __shfl_sync(0xffffffffu, ex, 2);
        float w3 = __shfl_sync(0xffffffffu, ex, 3);
        float wa = (lane < 16) ? w0 : w1;       // heads 0/1 for float4 idx = lane
        float wb = (lane < 16) ? w2 : w3;       // heads 2/3 for float4 idx = lane+32
        const float4* hs = (const float4*)&d_h1[(size_t)s * 256];
        float4 a = hs[lane];
        float4 b = hs[lane + 32];
        accA.x += a.x * wa; accA.y += a.y * wa; accA.z += a.z * wa; accA.w += a.w * wa;
        accB.x += b.x * wb; accB.y += b.y * wb; accB.z += b.z * wb; accB.w += b.w * wb;
    }
    float s0 = __shfl_sync(0xffffffffu, wsum, 0);
    float s1 = __shfl_sync(0xffffffffu, wsum, 1);
    float s2 = __shfl_sync(0xffffffffu, wsum, 2);
    float s3 = __shfl_sync(0xffffffffu, wsum, 3);
    float inva = 1.f / (((lane < 16) ? s0 : s1) + 1e-16f);
    float invb = 1.f / (((lane < 16) ? s2 : s3) + 1e-16f);
    accA.x = elu_f(accA.x * inva); accA.y = elu_f(accA.y * inva);
    accA.z = elu_f(accA.z * inva); accA.w = elu_f(accA.w * inva);
    accB.x = elu_f(accB.x * invb); accB.y = elu_f(accB.y * invb);
    accB.z = elu_f(accB.z * invb); accB.w = elu_f(accB.w * invb);
    float* xr = &d_x2[(size_t)n * 256];
    *(float4*)&xr[lane * 4] = accA;
    *(float4*)&xr[128 + lane * 4] = accB;
    if (lane == 31)   // feature 255 -> layer2 guidance
        d_g2[n] = -0.1f * logf(fabsf(accB.w) + 1e-6f);
}

// ---------------- layer2 node prep: al2/ar2 dots ------------------------------
__global__ void node_prep2(const float* __restrict__ attl,
                           const float* __restrict__ attr, int N) {
    int w = (blockIdx.x * blockDim.x + threadIdx.x) >> 5;
    int lane = threadIdx.x & 31;
    if (w >= N) return;
    float aL = 0.f, aR = 0.f;
    #pragma unroll
    for (int i = 0; i < 2; i++) {
        int idx = lane + i * 32;
        float hv = d_h2[(size_t)w * 64 + idx];
        aL += hv * attl[idx];
        aR += hv * attr[idx];
    }
    #pragma unroll
    for (int off = 16; off; off >>= 1) {
        aL += __shfl_xor_sync(0xffffffffu, aL, off);
        aR += __shfl_xor_sync(0xffffffffu, aR, off);
    }
    if (lane == 0) { d_al2[w] = aL; d_ar2[w] = aR; }
}

// ---------------- layer2 CSR aggregation + normalize + ELU + final FC ---------
__global__ void agg2_csr(const float* __restrict__ fcw, const float* __restrict__ fcb,
                         float* __restrict__ out, int N) {
    int n = (blockIdx.x * blockDim.x + threadIdx.x) >> 5;
    int lane = threadIdx.x & 31;
    if (n >= N) return;
    int beg = d_rs[n], end = d_rs[n + 1];
    float aln = d_al2[n];
    float2 acc = make_float2(0.f, 0.f);
    float wsum = 0.f;
    for (int p = beg; p < end; p++) {
        int s = d_srcs[p];
        float ex = 0.f;
        if (lane == 0) {
            float v = aln + d_ar2[s];
            v = v > 0.f ? v : 0.01f * v;
            v += d_g2[s];
            ex = __expf(v);
            wsum += ex;
        }
        ex = __shfl_sync(0xffffffffu, ex, 0);
        float2 hv = ((const float2*)&d_h2[(size_t)s * 64])[lane];
        acc.x += hv.x * ex;
        acc.y += hv.y * ex;
    }
    wsum = __shfl_sync(0xffffffffu, wsum, 0);
    float inv = 1.f / (wsum + 1e-16f);
    float v0 = elu_f(acc.x * inv);
    float v1 = elu_f(acc.y * inv);
    float dot = v0 * fcw[2 * lane] + v1 * fcw[2 * lane + 1];
    #pragma unroll
    for (int off = 16; off; off >>= 1)
        dot += __shfl_xor_sync(0xffffffffu, dot, off);
    if (lane == 0) out[n] = dot + fcb[0];
}

// ---------------- host launcher ----------------------------------------------
extern "C" void kernel_launch(void* const* d_in, const int* in_sizes, int n_in,
                              void* d_out, int out_size) {
    const float* x     = (const float*)d_in[0];
    const int*   ei    = (const int*)d_in[1];
    const float* W1    = (const float*)d_in[2];
    const float* attl1 = (const float*)d_in[3];
    const float* attr1 = (const float*)d_in[4];
    const float* W2    = (const float*)d_in[5];
    const float* attl2 = (const float*)d_in[6];
    const float* attr2 = (const float*)d_in[7];
    const float* fcw   = (const float*)d_in[8];
    const float* fcb   = (const float*)d_in[9];
    float* out = (float*)d_out;

    int N = in_sizes[0] / 128;
    int E = in_sizes[1] / 2;
    const int* src = ei;
    const int* dst = ei + E;

    void *ph1, *ph2, *px2, *pdeg, *pcur;
    cudaGetSymbolAddress(&ph1, d_h1);
    cudaGetSymbolAddress(&ph2, d_h2);
    cudaGetSymbolAddress(&px2, d_x2);
    cudaGetSymbolAddress(&pdeg, d_deg);
    cudaGetSymbolAddress(&pcur, d_cur);

    const int TB = 256;
    int gy = (N + 63) / 64;
    int nb = (N + SB - 1) / SB;

    // ---- CSR build (dst-sorted edges) ----
    cudaMemsetAsync(pdeg, 0, sizeof(int) * (size_t)N, 0);
    cudaMemsetAsync(pcur, 0, sizeof(int) * (size_t)N, 0);
    k_count<<<(E + TB - 1) / TB, TB>>>(dst, E);
    k_scan1<<<nb, SB>>>(N);
    k_scan2<<<1, 32>>>(nb, E);
    k_scan3<<<nb, SB>>>(N, E);
    k_scatter<<<(E + TB - 1) / TB, TB>>>(src, dst, E);

    // ---- layer 1 ----
    sgemm64<<<dim3(4, gy), TB>>>(x, W1, (float*)ph1, N, 128, 256);
    node_prep1<<<(N * 32 + TB - 1) / TB, TB>>>(x, attl1, attr1, N);
    agg1_csr<<<(N * 32 + TB - 1) / TB, TB>>>(N);

    // ---- layer 2 ----
    sgemm64<<<dim3(1, gy), TB>>>((const float*)px2, W2, (float*)ph2, N, 256, 64);
    node_prep2<<<(N * 32 + TB - 1) / TB, TB>>>(attl2, attr2, N);
    agg2_csr<<<(N * 32 + TB - 1) / TB, TB>>>(fcw, fcb, out, N);
}